// round 4
// baseline (speedup 1.0000x reference)
#include <cuda_runtime.h>
#include <math.h>

#define GW      128   // worker CTAs (MLP rows)
#define GRID    129   // workers + 1 dedicated state CTA
#define TPB     256
#define HID     1024
#define NH      256
#define NSTATE  17
#define NX      273
#define NXP     288   // NX padded to float4 multiple
#define TLEN    64
#define SUBSTEPS 8
#define ROWS0   8    // 1024/128 layer0 rows per worker CTA
#define ROWSH   8    // hidden rows per worker CTA
#define ROWSL   2    // 256/128 final rows per worker CTA

// persistent global scratch (no allocations allowed)
__device__ float g_y[NX];
__device__ float g_k[2][NX];
__device__ float g_acc[NX];
__device__ float g_z[2][HID];
__device__ unsigned g_arrive;
__device__ volatile unsigned g_gen;

__device__ __forceinline__ void gbar() {
    __syncthreads();
    if (threadIdx.x == 0) {
        unsigned gen = g_gen;
        __threadfence();   // make this CTA's writes globally visible (cumulative)
        if (atomicAdd(&g_arrive, 1u) == GRID - 1u) {
            g_arrive = 0u;
            __threadfence();
            g_gen = gen + 1u;
        } else {
            while (g_gen == gen) { }
            __threadfence(); // CCTL.IVALL: drop stale L1 lines before data reads
        }
    }
    __syncthreads();
}

__device__ __forceinline__ float warp_sum(float v) {
    v += __shfl_down_sync(0xffffffffu, v, 16);
    v += __shfl_down_sync(0xffffffffu, v, 8);
    v += __shfl_down_sync(0xffffffffu, v, 4);
    v += __shfl_down_sync(0xffffffffu, v, 2);
    v += __shfl_down_sync(0xffffffffu, v, 1);
    return v;
}

__device__ __forceinline__ float softplus_f(float v) {
    return fmaxf(v, 0.0f) + log1pf(expf(-fabsf(v)));
}

__device__ __forceinline__ float dot4(float4 a, float4 b) {
    return a.x*b.x + a.y*b.y + a.z*b.z + a.w*b.w;
}

extern __shared__ float smem[];
// layout: sWh[3*ROWSH*HID] | sW0[ROWS0*NXP] | sWl[ROWSL*HID] | xs[HID] | sst[32]
#define OFF_W0  (3*ROWSH*HID)
#define OFF_WL  (OFF_W0 + ROWS0*NXP)
#define OFF_XS  (OFF_WL + ROWSL*HID)
#define OFF_SST (OFF_XS + HID)
#define SMEM_FLOATS (OFF_SST + 32)

__global__ void __launch_bounds__(TPB, 1) ode_kernel(
    const float* __restrict__ ts,   const float* __restrict__ W0,
    const float* __restrict__ b0,   const float* __restrict__ Wh,
    const float* __restrict__ bh,   const float* __restrict__ Wl,
    const float* __restrict__ bl,   const float* __restrict__ betaW,
    const float* __restrict__ betab,const float* __restrict__ hvec,
    const float* __restrict__ scale,const float* __restrict__ y0log,
    float* __restrict__ out)
{
    const int b    = blockIdx.x;
    const int tid  = threadIdx.x;
    const int w    = tid >> 5;
    const int lane = tid & 31;
    const bool worker = (b < GW);

    float* sWh = smem;
    float* sW0 = smem + OFF_W0;
    float* sWl = smem + OFF_WL;
    float* xs  = smem + OFF_XS;
    float* sst = smem + OFF_SST;

    float bias0 = 0.0f, biasL = 0.0f;
    float biasH[3] = {0.0f, 0.0f, 0.0f};

    if (worker) {
        // ---- stage weight slices into SMEM (once per launch) ----
        float4* dst = (float4*)sWh;
        #pragma unroll
        for (int l = 0; l < 3; l++) {
            #pragma unroll
            for (int r = 0; r < ROWSH; r++) {
                const float4* src = (const float4*)(Wh + ((size_t)l*HID + (size_t)b*ROWSH + r)*HID);
                dst[(l*ROWSH + r)*(HID/4) + tid] = src[tid];   // HID/4 == TPB
            }
        }
        const float* w0src = W0 + (size_t)b*ROWS0*NX;
        #pragma unroll
        for (int r = 0; r < ROWS0; r++)
            for (int j = tid; j < NXP; j += TPB)
                sW0[r*NXP + j] = (j < NX) ? w0src[r*NX + j] : 0.0f;
        const float4* wlsrc = (const float4*)(Wl + (size_t)b*ROWSL*HID);
        float4* wldst = (float4*)sWl;
        #pragma unroll
        for (int r = 0; r < ROWSL; r++) wldst[r*(HID/4) + tid] = wlsrc[r*(HID/4) + tid];

        // biases in registers
        bias0 = b0[b*ROWS0 + w];
        #pragma unroll
        for (int l = 0; l < 3; l++) biasH[l] = bh[l*HID + b*ROWSH + w];
        if (w < ROWSL) biasL = bl[b*ROWSL + w];
    }

    // ---- init y0 = [softmax(y0log), hvec]; write output row 0 ----
    float* outS = out;                 // (64,17)
    float* outH = out + TLEN*NSTATE;   // (64,256)
    if (b == 0) {
        if (w == 0) {
            float e = (lane < NSTATE) ? expf(y0log[lane]) : 0.0f;
            float s = warp_sum(e);
            s = __shfl_sync(0xffffffffu, s, 0);
            if (lane < NSTATE) {
                float p = e / s;
                g_y[lane] = p;
                outS[lane] = p;
            }
        }
        for (int j = tid; j < NH; j += TPB) {
            float hv = hvec[j];
            g_y[NSTATE + j] = hv;
            outH[j] = hv;
        }
    }
    const float betab0 = betab[0];
    const float scale0 = scale[0];

    const float xi    = 13.0f/12.0f;
    const float mu    = 0.041f/12.0f;
    const float sig   = 91.0f/12.0f;
    const float nuc   = 36.0f/12.0f;
    const float gam   = 1.8f/12.0f;

    gbar();   // y0 + weights visible everywhere

    unsigned sc = 0;  // global stage counter (parity selects k ping-pong)
    for (int iv = 0; iv < TLEN-1; iv++) {
        const float dt = (ts[iv+1] - ts[iv]) * (1.0f/(float)SUBSTEPS);
        for (int ss = 0; ss < SUBSTEPS; ss++) {
            for (int st = 0; st < 4; st++) {
                const float a = (st == 0) ? 0.0f : ((st == 3) ? 1.0f : 0.5f);
                const float* kp = g_k[sc & 1u];
                float*       kn = g_k[(sc + 1u) & 1u];

                // ===== Phase A: stage x = [h_eval, state_eval]; layer0 (workers);
                //       beta/dstate/RK4-state (state CTA) =====
                for (int j = tid; j < NXP; j += TPB) {
                    float v = 0.0f;
                    if (j < NX) {
                        int src = (j < NH) ? (NSTATE + j) : (j - NH);
                        v = g_y[src];
                        if (st != 0) v += a * dt * kp[src];
                    }
                    xs[j] = v;   // pad region re-zeroed every stage
                }
                __syncthreads();
                if (worker) {
                    const float4* wr4 = (const float4*)(sW0 + w*NXP);
                    const float4* xs4 = (const float4*)xs;
                    float acc = dot4(wr4[lane],      xs4[lane])
                              + dot4(wr4[lane + 32], xs4[lane + 32]);
                    if (lane < (NXP/4 - 64))
                        acc += dot4(wr4[64 + lane], xs4[64 + lane]);
                    acc = warp_sum(acc);
                    if (lane == 0) g_z[0][b*ROWS0 + w] = softplus_f(acc + bias0);
                } else if (w == 0) {
                    const float4* bw4 = (const float4*)betaW;
                    const float4* xs4 = (const float4*)xs;
                    float part = dot4(bw4[lane],      xs4[lane])
                               + dot4(bw4[lane + 32], xs4[lane + 32]);
                    part = warp_sum(part);
                    if (lane < NSTATE) sst[lane] = xs[NH + lane];
                    __syncwarp();
                    if (lane == 0) {
                        float bb1 = 8.0f/(1.0f + expf(-(part + betab0))) + 25.0f;
                        float bb2 = 0.5f*bb1, bb3 = 0.35f*bb1, bb4 = 0.25f*bb1;
                        float M =sst[0],  S1=sst[1],  E1=sst[2],  E2=sst[3];
                        float E3=sst[4],  E4=sst[5],  I1=sst[6],  I2=sst[7];
                        float I3=sst[8],  I4=sst[9],  R1=sst[10], R2=sst[11];
                        float R3=sst[12], R4=sst[13], S2=sst[14], S3=sst[15];
                        float S4=sst[16];
                        float I = I1+I2+I3+I4;
                        float R = R1+R2+R3+R4;
                        float d[NSTATE];
                        d[0]  = R*mu - (xi+mu)*M;
                        d[1]  = mu*(1.0f-R) + xi*M - mu*S1 - bb1*I*S1;
                        d[2]  = bb1*I*S1 - (mu+sig)*E1;
                        d[3]  = bb2*I*S2 - (mu+sig)*E2;
                        d[4]  = bb3*I*S3 - (mu+sig)*E3;
                        d[5]  = bb4*I*S4 - (mu+sig)*E4;
                        d[6]  = sig*E1 - (nuc+mu)*I1;
                        d[7]  = sig*E2 - (nuc+mu)*I2;
                        d[8]  = sig*E3 - (nuc+mu)*I3;
                        d[9]  = sig*E4 - (nuc+mu)*I4;
                        d[10] = nuc*I1 - (mu+gam)*R1;
                        d[11] = nuc*I2 - (mu+gam)*R2;
                        d[12] = nuc*I3 - (mu+gam)*R3;
                        d[13] = nuc*I4 - (mu+gam)*R4;
                        d[14] = gam*R1 - mu*S2 - bb2*I*S2;
                        d[15] = gam*R2 - mu*S3 - bb3*I*S3;
                        d[16] = gam*(R3+R4) - mu*S4 - bb4*I*S4;
                        #pragma unroll
                        for (int i = 0; i < NSTATE; i++) {
                            float kv = d[i];
                            kn[i] = kv;
                            if (st == 0)      g_acc[i] = kv;
                            else if (st < 3)  g_acc[i] += 2.0f*kv;
                            else {
                                // defer g_y state write (workers may still be
                                // reading g_y in Phase A); commit in Phase E
                                sst[i] = g_y[i] + dt*(1.0f/6.0f)*(g_acc[i] + kv);
                            }
                        }
                    }
                }
                gbar();

                // ===== Phases B/C/D: hidden layers from SMEM weights =====
                #pragma unroll
                for (int l = 0; l < 3; l++) {
                    if (worker) {
                        const float4* zin4 = (const float4*)g_z[l & 1];
                        float4* xs4 = (float4*)xs;
                        xs4[tid] = zin4[tid];
                        __syncthreads();
                        const int r = b*ROWSH + w;
                        const float4* wr = (const float4*)(sWh + (l*ROWSH + w)*HID);
                        float acc = 0.0f;
                        #pragma unroll
                        for (int kk = 0; kk < 8; kk++)
                            acc += dot4(wr[lane + 32*kk], xs4[lane + 32*kk]);
                        acc = warp_sum(acc);
                        if (lane == 0) g_z[(l+1) & 1][r] = softplus_f(acc + biasH[l]);
                    }
                    gbar();
                }

                // ===== Phase E: Wl + tanh + RK4 fold (h, workers) + state commit =====
                if (worker) {
                    const float4* zin4 = (const float4*)g_z[1];   // z4 lives in g_z[1]
                    float4* xs4 = (float4*)xs;
                    xs4[tid] = zin4[tid];
                    __syncthreads();
                    if (w < ROWSL) {
                        const int r = b*ROWSL + w;
                        const float4* wr = (const float4*)(sWl + w*HID);
                        float acc = 0.0f;
                        #pragma unroll
                        for (int kk = 0; kk < 8; kk++)
                            acc += dot4(wr[lane + 32*kk], xs4[lane + 32*kk]);
                        acc = warp_sum(acc);
                        if (lane == 0) {
                            float kv = scale0 * tanhf(0.01f*(acc + biasL));
                            const int j = NSTATE + r;
                            kn[j] = kv;
                            if (st == 0)      g_acc[j] = kv;
                            else if (st < 3)  g_acc[j] += 2.0f*kv;
                            else {
                                float yn = g_y[j] + dt*(1.0f/6.0f)*(g_acc[j] + kv);
                                g_y[j] = yn;
                                if (ss == SUBSTEPS-1) outH[(iv+1)*NH + r] = yn;
                            }
                        }
                    }
                } else if (st == 3 && w == 0 && lane < NSTATE) {
                    // state CTA: commit deferred y-state update (race-free:
                    // workers re-read g_y states only after the gbar below)
                    float yn = sst[lane];
                    g_y[lane] = yn;
                    if (ss == SUBSTEPS-1) outS[(iv+1)*NSTATE + lane] = yn;
                }
                gbar();
                sc++;
            }
        }
    }
}

extern "C" void kernel_launch(void* const* d_in, const int* in_sizes, int n_in,
                              void* d_out, int out_size) {
    (void)in_sizes; (void)n_in; (void)out_size;
    const float* ts    = (const float*)d_in[0];
    const float* W0    = (const float*)d_in[1];
    const float* b0    = (const float*)d_in[2];
    const float* Wh    = (const float*)d_in[3];
    const float* bh    = (const float*)d_in[4];
    const float* Wl    = (const float*)d_in[5];
    const float* bl    = (const float*)d_in[6];
    const float* betaW = (const float*)d_in[7];
    const float* betab = (const float*)d_in[8];
    const float* hvec  = (const float*)d_in[9];
    const float* scale = (const float*)d_in[10];
    const float* y0log = (const float*)d_in[11];
    float* out = (float*)d_out;

    const size_t smem_bytes = (size_t)SMEM_FLOATS * sizeof(float);
    cudaFuncSetAttribute(ode_kernel, cudaFuncAttributeMaxDynamicSharedMemorySize,
                         (int)smem_bytes);
    ode_kernel<<<GRID, TPB, smem_bytes>>>(ts, W0, b0, Wh, bh, Wl, bl,
                                          betaW, betab, hvec, scale, y0log, out);
}

// round 5
// speedup vs baseline: 1.1036x; 1.1036x over previous
#include <cuda_runtime.h>
#include <math.h>

#define GW      128   // worker CTAs (MLP rows)
#define GRID    129   // workers + 1 dedicated state CTA
#define TPB     256
#define HID     1024
#define NH      256
#define NSTATE  17
#define NX      273
#define NXP     288   // NX padded to float4 multiple
#define TLEN    64
#define SUBSTEPS 8
#define ROWS0   8
#define ROWSH   8
#define ROWSL   2

// persistent global scratch (no allocations allowed)
__device__ float g_y[NX];
__device__ float g_k[2][NX];
__device__ float g_acc[NX];
__device__ float g_z[2][HID];
__device__ __align__(256) unsigned g_arrive;
__device__ __align__(256) unsigned g_gen;

// CG-style release/acquire grid barrier: no MEMBAR, no L1 flush.
// target must increase monotonically from 1; g_gen/g_arrive zeroed by prekernel.
__device__ __forceinline__ void gbar(unsigned target) {
    __syncthreads();
    if (threadIdx.x == 0) {
        unsigned prev;
        asm volatile("atom.release.gpu.add.u32 %0, [%1], %2;"
                     : "=r"(prev) : "l"(&g_arrive), "r"(1u) : "memory");
        if (prev == GRID - 1u) {
            asm volatile("st.relaxed.gpu.u32 [%0], %1;" :: "l"(&g_arrive), "r"(0u) : "memory");
            asm volatile("st.release.gpu.u32 [%0], %1;" :: "l"(&g_gen), "r"(target) : "memory");
        } else {
            unsigned v;
            do {
                asm volatile("ld.acquire.gpu.u32 %0, [%1];" : "=r"(v) : "l"(&g_gen) : "memory");
            } while (v != target);
        }
    }
    __syncthreads();
}

__device__ __forceinline__ float warp_sum(float v) {
    v += __shfl_down_sync(0xffffffffu, v, 16);
    v += __shfl_down_sync(0xffffffffu, v, 8);
    v += __shfl_down_sync(0xffffffffu, v, 4);
    v += __shfl_down_sync(0xffffffffu, v, 2);
    v += __shfl_down_sync(0xffffffffu, v, 1);
    return v;
}

__device__ __forceinline__ float softplus_f(float v) {
    return fmaxf(v, 0.0f) + log1pf(expf(-fabsf(v)));
}

__device__ __forceinline__ float dot4(float4 a, float4 b) {
    return a.x*b.x + a.y*b.y + a.z*b.z + a.w*b.w;
}

extern __shared__ float smem[];
#define OFF_W0  (3*ROWSH*HID)
#define OFF_WL  (OFF_W0 + ROWS0*NXP)
#define OFF_XS  (OFF_WL + ROWSL*HID)
#define OFF_SST (OFF_XS + HID)
#define SMEM_FLOATS (OFF_SST + 32)

__global__ void reset_kernel() {
    g_arrive = 0u;
    g_gen = 0u;
}

__global__ void __launch_bounds__(TPB, 1) ode_kernel(
    const float* __restrict__ ts,   const float* __restrict__ W0,
    const float* __restrict__ b0,   const float* __restrict__ Wh,
    const float* __restrict__ bh,   const float* __restrict__ Wl,
    const float* __restrict__ bl,   const float* __restrict__ betaW,
    const float* __restrict__ betab,const float* __restrict__ hvec,
    const float* __restrict__ scale,const float* __restrict__ y0log,
    float* __restrict__ out)
{
    const int b    = blockIdx.x;
    const int tid  = threadIdx.x;
    const int w    = tid >> 5;
    const int lane = tid & 31;
    const bool worker = (b < GW);

    float* sWh = smem;
    float* sW0 = smem + OFF_W0;
    float* sWl = smem + OFF_WL;
    float* xs  = smem + OFF_XS;
    float* sst = smem + OFF_SST;

    float bias0 = 0.0f, biasL = 0.0f;
    float biasH[3] = {0.0f, 0.0f, 0.0f};

    if (worker) {
        float4* dst = (float4*)sWh;
        #pragma unroll
        for (int l = 0; l < 3; l++) {
            #pragma unroll
            for (int r = 0; r < ROWSH; r++) {
                const float4* src = (const float4*)(Wh + ((size_t)l*HID + (size_t)b*ROWSH + r)*HID);
                dst[(l*ROWSH + r)*(HID/4) + tid] = src[tid];   // HID/4 == TPB
            }
        }
        const float* w0src = W0 + (size_t)b*ROWS0*NX;
        #pragma unroll
        for (int r = 0; r < ROWS0; r++)
            for (int j = tid; j < NXP; j += TPB)
                sW0[r*NXP + j] = (j < NX) ? w0src[r*NX + j] : 0.0f;
        const float4* wlsrc = (const float4*)(Wl + (size_t)b*ROWSL*HID);
        float4* wldst = (float4*)sWl;
        #pragma unroll
        for (int r = 0; r < ROWSL; r++) wldst[r*(HID/4) + tid] = wlsrc[r*(HID/4) + tid];

        bias0 = b0[b*ROWS0 + w];
        #pragma unroll
        for (int l = 0; l < 3; l++) biasH[l] = bh[l*HID + b*ROWSH + w];
        if (w < ROWSL) biasL = bl[b*ROWSL + w];
    }

    float* outS = out;                 // (64,17)
    float* outH = out + TLEN*NSTATE;   // (64,256)
    if (b == 0) {
        if (w == 0) {
            float e = (lane < NSTATE) ? expf(y0log[lane]) : 0.0f;
            float s = warp_sum(e);
            s = __shfl_sync(0xffffffffu, s, 0);
            if (lane < NSTATE) {
                float p = e / s;
                g_y[lane] = p;
                outS[lane] = p;
            }
        }
        for (int j = tid; j < NH; j += TPB) {
            float hv = hvec[j];
            g_y[NSTATE + j] = hv;
            outH[j] = hv;
        }
    }
    const float betab0 = betab[0];
    const float scale0 = scale[0];

    const float xi    = 13.0f/12.0f;
    const float mu    = 0.041f/12.0f;
    const float sig   = 91.0f/12.0f;
    const float nuc   = 36.0f/12.0f;
    const float gam   = 1.8f/12.0f;

    unsigned gen = 0;
    gbar(++gen);   // y0 + weights visible everywhere

    unsigned sc = 0;
    for (int iv = 0; iv < TLEN-1; iv++) {
        const float dt = (ts[iv+1] - ts[iv]) * (1.0f/(float)SUBSTEPS);
        for (int ss = 0; ss < SUBSTEPS; ss++) {
            for (int st = 0; st < 4; st++) {
                const float a = (st == 0) ? 0.0f : ((st == 3) ? 1.0f : 0.5f);
                const float* kp = g_k[sc & 1u];
                float*       kn = g_k[(sc + 1u) & 1u];

                // ===== Phase A: stage x; layer0 (workers); beta/dstate (state CTA) =====
                for (int j = tid; j < NXP; j += TPB) {
                    float v = 0.0f;
                    if (j < NX) {
                        int src = (j < NH) ? (NSTATE + j) : (j - NH);
                        v = __ldcv(&g_y[src]);                 // cross-CTA: bypass L1
                        if (st != 0) v += a * dt * __ldcv(&kp[src]);
                    }
                    xs[j] = v;
                }
                __syncthreads();
                if (worker) {
                    const float4* wr4 = (const float4*)(sW0 + w*NXP);
                    const float4* xs4 = (const float4*)xs;
                    float acc = dot4(wr4[lane],      xs4[lane])
                              + dot4(wr4[lane + 32], xs4[lane + 32]);
                    if (lane < (NXP/4 - 64))
                        acc += dot4(wr4[64 + lane], xs4[64 + lane]);
                    acc = warp_sum(acc);
                    if (lane == 0) g_z[0][b*ROWS0 + w] = softplus_f(acc + bias0);
                } else if (w == 0) {
                    const float4* bw4 = (const float4*)betaW;
                    const float4* xs4 = (const float4*)xs;
                    float part = dot4(bw4[lane],      xs4[lane])
                               + dot4(bw4[lane + 32], xs4[lane + 32]);
                    part = warp_sum(part);
                    if (lane < NSTATE) sst[lane] = xs[NH + lane];
                    __syncwarp();
                    if (lane == 0) {
                        float bb1 = 8.0f/(1.0f + expf(-(part + betab0))) + 25.0f;
                        float bb2 = 0.5f*bb1, bb3 = 0.35f*bb1, bb4 = 0.25f*bb1;
                        float M =sst[0],  S1=sst[1],  E1=sst[2],  E2=sst[3];
                        float E3=sst[4],  E4=sst[5],  I1=sst[6],  I2=sst[7];
                        float I3=sst[8],  I4=sst[9],  R1=sst[10], R2=sst[11];
                        float R3=sst[12], R4=sst[13], S2=sst[14], S3=sst[15];
                        float S4=sst[16];
                        float I = I1+I2+I3+I4;
                        float R = R1+R2+R3+R4;
                        float d[NSTATE];
                        d[0]  = R*mu - (xi+mu)*M;
                        d[1]  = mu*(1.0f-R) + xi*M - mu*S1 - bb1*I*S1;
                        d[2]  = bb1*I*S1 - (mu+sig)*E1;
                        d[3]  = bb2*I*S2 - (mu+sig)*E2;
                        d[4]  = bb3*I*S3 - (mu+sig)*E3;
                        d[5]  = bb4*I*S4 - (mu+sig)*E4;
                        d[6]  = sig*E1 - (nuc+mu)*I1;
                        d[7]  = sig*E2 - (nuc+mu)*I2;
                        d[8]  = sig*E3 - (nuc+mu)*I3;
                        d[9]  = sig*E4 - (nuc+mu)*I4;
                        d[10] = nuc*I1 - (mu+gam)*R1;
                        d[11] = nuc*I2 - (mu+gam)*R2;
                        d[12] = nuc*I3 - (mu+gam)*R3;
                        d[13] = nuc*I4 - (mu+gam)*R4;
                        d[14] = gam*R1 - mu*S2 - bb2*I*S2;
                        d[15] = gam*R2 - mu*S3 - bb3*I*S3;
                        d[16] = gam*(R3+R4) - mu*S4 - bb4*I*S4;
                        #pragma unroll
                        for (int i = 0; i < NSTATE; i++) {
                            float kv = d[i];
                            kn[i] = kv;
                            if (st == 0)      g_acc[i] = kv;
                            else if (st < 3)  g_acc[i] += 2.0f*kv;
                            else {
                                // defer g_y state commit to Phase E (race with
                                // workers' Phase-A reads of g_y otherwise)
                                sst[i] = __ldcv(&g_y[i]) + dt*(1.0f/6.0f)*(g_acc[i] + kv);
                            }
                        }
                    }
                }
                gbar(++gen);

                // ===== Phases B/C/D: hidden layers from SMEM weights =====
                #pragma unroll
                for (int l = 0; l < 3; l++) {
                    if (worker) {
                        const float4* zin4 = (const float4*)g_z[l & 1];
                        float4* xs4 = (float4*)xs;
                        xs4[tid] = __ldcv(zin4 + tid);         // cross-CTA
                        __syncthreads();
                        const int r = b*ROWSH + w;
                        const float4* wr = (const float4*)(sWh + (l*ROWSH + w)*HID);
                        float acc = 0.0f;
                        #pragma unroll
                        for (int kk = 0; kk < 8; kk++)
                            acc += dot4(wr[lane + 32*kk], xs4[lane + 32*kk]);
                        acc = warp_sum(acc);
                        if (lane == 0) g_z[(l+1) & 1][r] = softplus_f(acc + biasH[l]);
                    }
                    gbar(++gen);
                }

                // ===== Phase E: Wl + tanh + RK4 fold (workers) + state commit =====
                if (worker) {
                    const float4* zin4 = (const float4*)g_z[1];
                    float4* xs4 = (float4*)xs;
                    xs4[tid] = __ldcv(zin4 + tid);             // cross-CTA
                    __syncthreads();
                    if (w < ROWSL) {
                        const int r = b*ROWSL + w;
                        const float4* wr = (const float4*)(sWl + w*HID);
                        float acc = 0.0f;
                        #pragma unroll
                        for (int kk = 0; kk < 8; kk++)
                            acc += dot4(wr[lane + 32*kk], xs4[lane + 32*kk]);
                        acc = warp_sum(acc);
                        if (lane == 0) {
                            float kv = scale0 * tanhf(0.01f*(acc + biasL));
                            const int j = NSTATE + r;
                            kn[j] = kv;
                            if (st == 0)      g_acc[j] = kv;
                            else if (st < 3)  g_acc[j] += 2.0f*kv;
                            else {
                                float yn = g_y[j] + dt*(1.0f/6.0f)*(g_acc[j] + kv);
                                g_y[j] = yn;    // CTA-local row
                                if (ss == SUBSTEPS-1) outH[(iv+1)*NH + r] = yn;
                            }
                        }
                    }
                } else if (st == 3 && w == 0 && lane < NSTATE) {
                    float yn = sst[lane];
                    g_y[lane] = yn;
                    if (ss == SUBSTEPS-1) outS[(iv+1)*NSTATE + lane] = yn;
                }
                gbar(++gen);
                sc++;
            }
        }
    }
}

extern "C" void kernel_launch(void* const* d_in, const int* in_sizes, int n_in,
                              void* d_out, int out_size) {
    (void)in_sizes; (void)n_in; (void)out_size;
    const float* ts    = (const float*)d_in[0];
    const float* W0    = (const float*)d_in[1];
    const float* b0    = (const float*)d_in[2];
    const float* Wh    = (const float*)d_in[3];
    const float* bh    = (const float*)d_in[4];
    const float* Wl    = (const float*)d_in[5];
    const float* bl    = (const float*)d_in[6];
    const float* betaW = (const float*)d_in[7];
    const float* betab = (const float*)d_in[8];
    const float* hvec  = (const float*)d_in[9];
    const float* scale = (const float*)d_in[10];
    const float* y0log = (const float*)d_in[11];
    float* out = (float*)d_out;

    const size_t smem_bytes = (size_t)SMEM_FLOATS * sizeof(float);
    cudaFuncSetAttribute(ode_kernel, cudaFuncAttributeMaxDynamicSharedMemorySize,
                         (int)smem_bytes);
    reset_kernel<<<1, 1>>>();
    ode_kernel<<<GRID, TPB, smem_bytes>>>(ts, W0, b0, Wh, bh, Wl, bl,
                                          betaW, betab, hvec, scale, y0log, out);
}

// round 10
// speedup vs baseline: 1.4782x; 1.3395x over previous
#include <cuda_runtime.h>
#include <math.h>

#define GW      128   // worker CTAs
#define GRID    129   // + 1 state CTA
#define TPB     256
#define HID     1024
#define NH      256
#define NSTATE  17
#define NX      273
#define NXP     288
#define TLEN    64
#define SUBSTEPS 8
#define ROWSH   8
#define ROWSL   2

// tagged chunk buffers (ping-pong by stage parity everywhere)
__device__ float2 g_z8[2][4][HID];   // per-row z chunks: (value, tag)
__device__ float4 g_ec[2][NH];       // worker E-chunks: (k_h, y_h, 0, tag)
__device__ float4 g_scb[2][NSTATE];  // state chunks: (k_s, y_s, 0, tag)

#define POISON_TAG 0x80000000u
#define NPOISON (8*HID + 2*NH + 2*NSTATE)

__global__ void poison_kernel() {
    int i = blockIdx.x * blockDim.x + threadIdx.x;
    float bad = __uint_as_float(POISON_TAG);
    if (i < 8*HID) (&g_z8[0][0][0])[i] = make_float2(bad, bad);
    else if (i < 8*HID + 2*NH) (&g_ec[0][0])[i - 8*HID] = make_float4(bad, bad, bad, bad);
    else if (i < NPOISON)
        (&g_scb[0][0])[i - 8*HID - 2*NH] = make_float4(bad, bad, bad, bad);
}

// monotonic acceptance: tag_read - tag_wanted >= 0 (signed); poison is very negative
__device__ __forceinline__ bool tag_ok(float t, unsigned want) {
    return (int)(__float_as_uint(t) - want) >= 0;
}

__device__ __forceinline__ void store_z8(float2* p, float v, unsigned tag) {
    asm volatile("st.global.cg.v2.f32 [%0], {%1,%2};"
                 :: "l"(p), "f"(v), "f"(__uint_as_float(tag)) : "memory");
}

__device__ __forceinline__ float4 poll_chunk(const float4* p, unsigned tag) {
    float a, b, c, d;
    while (true) {
        asm volatile("ld.global.cv.v4.f32 {%0,%1,%2,%3}, [%4];"
                     : "=f"(a), "=f"(b), "=f"(c), "=f"(d) : "l"(p));
        if (tag_ok(d, tag)) break;
    }
    return make_float4(a, b, c, d);
}

__device__ __forceinline__ void store_chunk(float4* p, float a, float b, unsigned tag) {
    asm volatile("st.global.cg.v4.f32 [%0], {%1,%2,%3,%4};"
                 :: "l"(p), "f"(a), "f"(b), "f"(0.0f), "f"(__uint_as_float(tag)) : "memory");
}

// interleaved 4-chunk poll + scatter into xs (1024 rows, 256 threads)
__device__ __forceinline__ void poll_z8(const float2* buf, unsigned tag, float* xs, int tid) {
    unsigned done = 0;
    while (done != 0xFu) {
        #pragma unroll
        for (int q = 0; q < 4; q++) {
            if (!(done & (1u << q))) {
                float v, t;
                asm volatile("ld.global.cv.v2.f32 {%0,%1}, [%2];"
                             : "=f"(v), "=f"(t) : "l"(buf + tid + 256*q));
                if (tag_ok(t, tag)) { xs[tid + 256*q] = v; done |= 1u << q; }
            }
        }
    }
}

__device__ __forceinline__ float warp_sum(float v) {
    v += __shfl_down_sync(0xffffffffu, v, 16);
    v += __shfl_down_sync(0xffffffffu, v, 8);
    v += __shfl_down_sync(0xffffffffu, v, 4);
    v += __shfl_down_sync(0xffffffffu, v, 2);
    v += __shfl_down_sync(0xffffffffu, v, 1);
    return v;
}

__device__ __forceinline__ float softplus_f(float v) {
    return fmaxf(v, 0.0f) + log1pf(expf(-fabsf(v)));
}

__device__ __forceinline__ float dot4(float4 a, float4 b) {
    return a.x*b.x + a.y*b.y + a.z*b.z + a.w*b.w;
}

extern __shared__ float smem[];
#define OFF_W0   (3*ROWSH*HID)
#define OFF_WL   (OFF_W0 + ROWSH*NXP)
#define OFF_XS   (OFF_WL + ROWSL*HID)
#define OFF_SST  (OFF_XS + 2*HID)
#define SMEM_FLOATS (OFF_SST + 64)
// state CTA SMEM slots
#define YS 0
#define AC 17
#define KP 34

__global__ void __launch_bounds__(TPB, 1) ode_kernel(
    const float* __restrict__ ts,   const float* __restrict__ W0,
    const float* __restrict__ b0,   const float* __restrict__ Wh,
    const float* __restrict__ bh,   const float* __restrict__ Wl,
    const float* __restrict__ bl,   const float* __restrict__ betaW,
    const float* __restrict__ betab,const float* __restrict__ hvec,
    const float* __restrict__ scale,const float* __restrict__ y0log,
    float* __restrict__ out)
{
    const int b    = blockIdx.x;
    const int tid  = threadIdx.x;
    const int w    = tid >> 5;
    const int lane = tid & 31;
    const bool worker = (b < GW);

    float* sWh  = smem;
    float* sW0  = smem + OFF_W0;
    float* sWl  = smem + OFF_WL;
    float* xsb  = smem + OFF_XS;     // two 1024-float ping-pong buffers
    float* sst  = smem + OFF_SST;

    float* outS = out;                 // (64,17)
    float* outH = out + TLEN*NSTATE;   // (64,256)

    const float betab0 = betab[0];
    const float scale0 = scale[0];

    const float xi    = 13.0f/12.0f;
    const float mu    = 0.041f/12.0f;
    const float sig   = 91.0f/12.0f;
    const float nuc   = 36.0f/12.0f;
    const float gam   = 1.8f/12.0f;

    float bias0 = 0.0f, biasL = 0.0f;
    float biasH[3] = {0.0f, 0.0f, 0.0f};
    float e_y = 0.0f, e_acc = 0.0f;     // E-row regs (warps 0,1 lane 0)

    if (worker) {
        // ---- stage weight slices into SMEM ----
        float4* dst = (float4*)sWh;
        #pragma unroll
        for (int l = 0; l < 3; l++)
            #pragma unroll
            for (int r = 0; r < ROWSH; r++) {
                const float4* src = (const float4*)(Wh + ((size_t)l*HID + (size_t)b*ROWSH + r)*HID);
                dst[(l*ROWSH + r)*(HID/4) + tid] = src[tid];
            }
        const float* w0src = W0 + (size_t)b*ROWSH*NX;
        #pragma unroll
        for (int r = 0; r < ROWSH; r++)
            for (int j = tid; j < NXP; j += TPB)
                sW0[r*NXP + j] = (j < NX) ? w0src[r*NX + j] : 0.0f;
        const float4* wlsrc = (const float4*)(Wl + (size_t)b*ROWSL*HID);
        float4* wldst = (float4*)sWl;
        #pragma unroll
        for (int r = 0; r < ROWSL; r++) wldst[r*(HID/4) + tid] = wlsrc[r*(HID/4) + tid];

        bias0 = b0[b*ROWSH + w];
        #pragma unroll
        for (int l = 0; l < 3; l++) biasH[l] = bh[l*HID + b*ROWSH + w];
        if (w < ROWSL) biasL = bl[b*ROWSL + w];

        // prime E-chunks (tag 0)
        if (w < 2 && lane == 0) {
            e_y = hvec[2*b + w];
            outH[2*b + w] = e_y;
            store_chunk(&g_ec[0][2*b + w], 0.0f, e_y, 0u);
        }
    } else if (w == 0) {
        // state CTA: prime softmax(y0log) + state chunks (tag 0)
        float e = (lane < NSTATE) ? expf(y0log[lane]) : 0.0f;
        float s = warp_sum(e);
        s = __shfl_sync(0xffffffffu, s, 0);
        float p = e / s;
        if (lane < NSTATE) outS[lane] = p;
        #pragma unroll
        for (int q = 0; q < NSTATE; q++) {
            float pq = __shfl_sync(0xffffffffu, p, q);
            if (lane == 0) {
                sst[YS + q] = pq;
                sst[KP + q] = 0.0f;
                store_chunk(&g_scb[0][q], 0.0f, pq, 0u);
            }
        }
    }

    unsigned sc = 0;
    int pp = 0;   // xs ping-pong parity (toggled every phase)
    for (int iv = 0; iv < TLEN-1; iv++) {
        const float dt = (ts[iv+1] - ts[iv]) * (1.0f/(float)SUBSTEPS);
        for (int ss = 0; ss < SUBSTEPS; ss++) {
            for (int st = 0; st < 4; st++) {
                const float a  = (st == 0) ? 0.0f : ((st == 3) ? 1.0f : 0.5f);
                const float ad = a * dt;
                const int ebuf = sc & 1;
                float2 (*zbuf)[HID] = g_z8[sc & 1];   // z ping-pong by stage parity

                if (worker) {
                    // ===== Phase A: poll E+state chunks into xs; W0 dot =====
                    {
                        float* xa = xsb + pp*HID;
                        if (tid < NSTATE) {
                            const float4* pE = &g_ec[ebuf][tid];
                            const float4* pS = &g_scb[ebuf][tid];
                            bool gE = false, gS = false;
                            while (!(gE && gS)) {
                                if (!gE) {
                                    float x0,x1,x2,x3;
                                    asm volatile("ld.global.cv.v4.f32 {%0,%1,%2,%3}, [%4];"
                                                 : "=f"(x0),"=f"(x1),"=f"(x2),"=f"(x3) : "l"(pE));
                                    if (tag_ok(x3, sc)) { xa[tid] = fmaf(ad, x0, x1); gE = true; }
                                }
                                if (!gS) {
                                    float x0,x1,x2,x3;
                                    asm volatile("ld.global.cv.v4.f32 {%0,%1,%2,%3}, [%4];"
                                                 : "=f"(x0),"=f"(x1),"=f"(x2),"=f"(x3) : "l"(pS));
                                    if (tag_ok(x3, sc)) { xa[NH + tid] = fmaf(ad, x0, x1); gS = true; }
                                }
                            }
                        } else {
                            if (tid < 32) xa[NX + (tid - NSTATE)] = 0.0f;   // pad 273..287
                            float4 ch = poll_chunk(&g_ec[ebuf][tid], sc);
                            xa[tid] = fmaf(ad, ch.x, ch.y);
                        }
                        __syncthreads();
                        const float4* wr4 = (const float4*)(sW0 + w*NXP);
                        const float4* xs4 = (const float4*)xa;
                        float acc = dot4(wr4[lane],      xs4[lane])
                                  + dot4(wr4[lane + 32], xs4[lane + 32]);
                        if (lane < (NXP/4 - 64))
                            acc += dot4(wr4[64 + lane], xs4[64 + lane]);
                        acc = warp_sum(acc);
                        if (lane == 0)
                            store_z8(&zbuf[0][b*ROWSH + w], softplus_f(acc + bias0), sc);
                        pp ^= 1;
                    }

                    // ===== Phases B/C/D: hidden layers =====
                    #pragma unroll
                    for (int l = 0; l < 3; l++) {
                        float* xb = xsb + pp*HID;
                        poll_z8(zbuf[l], sc, xb, tid);
                        __syncthreads();
                        const float4* xs4 = (const float4*)xb;
                        const float4* wr  = (const float4*)(sWh + (l*ROWSH + w)*HID);
                        float acc = 0.0f;
                        #pragma unroll
                        for (int kk = 0; kk < 8; kk++)
                            acc += dot4(wr[lane + 32*kk], xs4[lane + 32*kk]);
                        acc = warp_sum(acc);
                        if (lane == 0)
                            store_z8(&zbuf[l+1][b*ROWSH + w], softplus_f(acc + biasH[l]), sc);
                        pp ^= 1;
                    }

                    // ===== Phase E: Wl + tanh + RK4 fold; publish E-chunks =====
                    {
                        float* xe = xsb + pp*HID;
                        poll_z8(zbuf[3], sc, xe, tid);
                        __syncthreads();
                        if (w < ROWSL) {
                            const float4* xs4 = (const float4*)xe;
                            const float4* wr  = (const float4*)(sWl + w*HID);
                            float acc = 0.0f;
                            #pragma unroll
                            for (int kk = 0; kk < 8; kk++)
                                acc += dot4(wr[lane + 32*kk], xs4[lane + 32*kk]);
                            acc = warp_sum(acc);
                            if (lane == 0) {
                                float kv = scale0 * tanhf(0.01f*(acc + biasL));
                                if (st == 0)      e_acc = kv;
                                else if (st < 3)  e_acc += 2.0f*kv;
                                else {
                                    e_y += dt*(1.0f/6.0f)*(e_acc + kv);
                                    if (ss == SUBSTEPS-1) outH[(iv+1)*NH + 2*b + w] = e_y;
                                }
                                store_chunk(&g_ec[(sc+1)&1][2*b + w], kv, e_y, sc+1);
                            }
                        }
                        pp ^= 1;
                    }
                } else {
                    // ===== state CTA: poll E chunks; beta + dstate + RK4 =====
                    float* xa = xsb;
                    {
                        float4 ch = poll_chunk(&g_ec[ebuf][tid], sc);
                        xa[tid] = fmaf(ad, ch.x, ch.y);
                    }
                    __syncthreads();
                    if (w == 0) {
                        const float4* bw4 = (const float4*)betaW;
                        const float4* xs4 = (const float4*)xa;
                        float part = dot4(bw4[lane],      xs4[lane])
                                   + dot4(bw4[lane + 32], xs4[lane + 32]);
                        part = warp_sum(part);
                        if (lane == 0) {
                            float sv[NSTATE];
                            #pragma unroll
                            for (int q = 0; q < NSTATE; q++)
                                sv[q] = fmaf(ad, sst[KP + q], sst[YS + q]);
                            float bb1 = 8.0f/(1.0f + expf(-(part + betab0))) + 25.0f;
                            float bb2 = 0.5f*bb1, bb3 = 0.35f*bb1, bb4 = 0.25f*bb1;
                            float M =sv[0],  S1=sv[1],  E1=sv[2],  E2=sv[3];
                            float E3=sv[4],  E4=sv[5],  I1=sv[6],  I2=sv[7];
                            float I3=sv[8],  I4=sv[9],  R1=sv[10], R2=sv[11];
                            float R3=sv[12], R4=sv[13], S2=sv[14], S3=sv[15];
                            float S4=sv[16];
                            float I = I1+I2+I3+I4;
                            float R = R1+R2+R3+R4;
                            float d[NSTATE];
                            d[0]  = R*mu - (xi+mu)*M;
                            d[1]  = mu*(1.0f-R) + xi*M - mu*S1 - bb1*I*S1;
                            d[2]  = bb1*I*S1 - (mu+sig)*E1;
                            d[3]  = bb2*I*S2 - (mu+sig)*E2;
                            d[4]  = bb3*I*S3 - (mu+sig)*E3;
                            d[5]  = bb4*I*S4 - (mu+sig)*E4;
                            d[6]  = sig*E1 - (nuc+mu)*I1;
                            d[7]  = sig*E2 - (nuc+mu)*I2;
                            d[8]  = sig*E3 - (nuc+mu)*I3;
                            d[9]  = sig*E4 - (nuc+mu)*I4;
                            d[10] = nuc*I1 - (mu+gam)*R1;
                            d[11] = nuc*I2 - (mu+gam)*R2;
                            d[12] = nuc*I3 - (mu+gam)*R3;
                            d[13] = nuc*I4 - (mu+gam)*R4;
                            d[14] = gam*R1 - mu*S2 - bb2*I*S2;
                            d[15] = gam*R2 - mu*S3 - bb3*I*S3;
                            d[16] = gam*(R3+R4) - mu*S4 - bb4*I*S4;
                            #pragma unroll
                            for (int q = 0; q < NSTATE; q++) {
                                float kv = d[q];
                                sst[KP + q] = kv;
                                if (st == 0)      sst[AC + q] = kv;
                                else if (st < 3)  sst[AC + q] += 2.0f*kv;
                                else {
                                    float yn = sst[YS + q] + dt*(1.0f/6.0f)*(sst[AC + q] + kv);
                                    sst[YS + q] = yn;
                                    if (ss == SUBSTEPS-1) outS[(iv+1)*NSTATE + q] = yn;
                                }
                                store_chunk(&g_scb[(sc+1)&1][q], kv, sst[YS + q], sc+1);
                            }
                        }
                    }
                    __syncthreads();
                }
                sc++;
            }
        }
    }
}

extern "C" void kernel_launch(void* const* d_in, const int* in_sizes, int n_in,
                              void* d_out, int out_size) {
    (void)in_sizes; (void)n_in; (void)out_size;
    const float* ts    = (const float*)d_in[0];
    const float* W0    = (const float*)d_in[1];
    const float* b0    = (const float*)d_in[2];
    const float* Wh    = (const float*)d_in[3];
    const float* bh    = (const float*)d_in[4];
    const float* Wl    = (const float*)d_in[5];
    const float* bl    = (const float*)d_in[6];
    const float* betaW = (const float*)d_in[7];
    const float* betab = (const float*)d_in[8];
    const float* hvec  = (const float*)d_in[9];
    const float* scale = (const float*)d_in[10];
    const float* y0log = (const float*)d_in[11];
    float* out = (float*)d_out;

    const size_t smem_bytes = (size_t)SMEM_FLOATS * sizeof(float);
    cudaFuncSetAttribute(ode_kernel, cudaFuncAttributeMaxDynamicSharedMemorySize,
                         (int)smem_bytes);
    poison_kernel<<<(NPOISON + TPB - 1)/TPB, TPB>>>();
    ode_kernel<<<GRID, TPB, smem_bytes>>>(ts, W0, b0, Wh, bh, Wl, bl,
                                          betaW, betab, hvec, scale, y0log, out);
}